// round 16
// baseline (speedup 1.0000x reference)
#include <cuda_runtime.h>
#include <cuda_bf16.h>
#include <math.h>
#include <stdint.h>

// Problem constants (fixed shapes)
#define N_SPOTS 10000
#define D_LAT   128
#define D_IN    3000
#define KNN_K   10
#define SCALE   6
#define BN_EPS  1e-4f

// KNN grid
#define GRID_D  40
#define CSZ     2.5f
#define INV_CSZ 0.4f
#define NCELLS  (GRID_D * GRID_D)
#define SLACK   0.5f

#define INF_F __int_as_float(0x7f800000)

// ---------------- scratch (device globals; no allocation allowed) -------------
__device__ int    g_idx[N_SPOTS * KNN_K];
__device__ int    g_cnt[NCELLS];
__device__ int    g_cur[NCELLS];
__device__ __align__(8)  int2   g_range[NCELLS];      // (start, count)
__device__ __align__(16) float4 g_sp4[N_SPOTS];       // (x, y, idx-bits, 0)
__device__ __align__(16) float g_G[D_LAT * D_LAT];    // Z^T Z
__device__ __align__(16) float g_s[D_LAT];            // col-sum of Z
__device__ __align__(16) float g_mu[D_IN];
__device__ __align__(16) float g_rs[D_IN];
// pre-split bf16 hi/lo operands (packed bf16x2 per k-pair), kpair-major for W
__device__ __align__(16) uint32_t g_zh[(size_t)N_SPOTS * 64];   // [row][kp]
__device__ __align__(16) uint32_t g_zl[(size_t)N_SPOTS * 64];
__device__ __align__(16) uint32_t g_bh[(size_t)64 * D_IN];      // [kp][n]
__device__ __align__(16) uint32_t g_bl[(size_t)64 * D_IN];

// lexicographic (d2, idx) compare: matches jax.lax.top_k stable tie-break
__device__ __forceinline__ bool lexless(float d1, int j1, float d2, int j2) {
    return (d1 < d2) || (d1 == d2 && j1 < j2);
}

__device__ __forceinline__ int cell_x(float x) {
    int c = (int)(x * INV_CSZ);
    return min(GRID_D - 1, max(0, c));
}

__device__ __forceinline__ void split_bf(float v, __nv_bfloat16& h, __nv_bfloat16& l) {
    h = __float2bfloat16_rn(v);
    l = __float2bfloat16_rn(v - __bfloat162float(h));
}

__device__ __forceinline__ uint32_t pack2(__nv_bfloat16 a, __nv_bfloat16 b) {
    __nv_bfloat162 t; t.x = a; t.y = b;     // .x = low 16 bits = lower-k element
    return *reinterpret_cast<uint32_t*>(&t);
}

// --------------------------- zero all scratch (1 launch) ------------------------
__global__ void zero_scratch() {
    const int i = blockIdx.x * 256 + threadIdx.x;
    if (i < NCELLS) { g_cnt[i] = 0; g_cur[i] = 0; }
    if (i < D_LAT)  g_s[i] = 0.0f;
    if (i < D_LAT * D_LAT) g_G[i] = 0.0f;
}

// ----------------------------- KNN: build grid ---------------------------------
__global__ void knn_count(const float2* __restrict__ sp) {
    const int i = blockIdx.x * 256 + threadIdx.x;
    if (i >= N_SPOTS) return;
    const float2 s = sp[i];
    atomicAdd(&g_cnt[cell_x(s.y) * GRID_D + cell_x(s.x)], 1);
}

// single-warp exclusive scan over 1600 cells
__global__ void knn_scan() {
    const int lane = threadIdx.x;           // 32 threads
    const int CH = NCELLS / 32;             // 50
    const int base = lane * CH;
    int s = 0;
    for (int k = 0; k < CH; k++) s += g_cnt[base + k];
    int inc = s;
#pragma unroll
    for (int o = 1; o < 32; o <<= 1) {
        int v = __shfl_up_sync(0xffffffffu, inc, o);
        if (lane >= o) inc += v;
    }
    int run = inc - s;
    for (int k = 0; k < CH; k++) {
        const int c = g_cnt[base + k];
        g_range[base + k] = make_int2(run, c);
        run += c;
    }
}

__global__ void knn_scatter(const float2* __restrict__ sp) {
    const int i = blockIdx.x * 256 + threadIdx.x;
    if (i >= N_SPOTS) return;
    const float2 s = sp[i];
    const int c = cell_x(s.y) * GRID_D + cell_x(s.x);
    const int dst = g_range[c].x + atomicAdd(&g_cur[c], 1);
    g_sp4[dst] = make_float4(s.x, s.y, __int_as_float(i), 0.0f);
}

// ----------------------------- KNN: ring search --------------------------------
// d2 BIT-EXACT vs reference (XLA lowers the K=2 dot without fma):
//   sq = rn(rn(x*x) + rn(y*y));  dot = rn(rn(xi*xj) + rn(yi*yj))
//   d2 = rn(rn(sqi + sqj) - 2*dot)
#define CBATCH 8
__device__ __forceinline__ void proc_span(const int2* __restrict__ sr, int ca, int cb,
                                          int i, float mx, float my, float sqi,
                                          float* dd, int* jj,
                                          float& wd, int& wj, int& ws) {
    const int2 ra = sr[ca];
    const int2 rb = sr[cb];
    int t = ra.x;
    const int t1 = rb.x + rb.y;
    while (t < t1) {
        const int nb = min(t1 - t, CBATCH);
        float4 buf[CBATCH];
#pragma unroll
        for (int u = 0; u < CBATCH; u++)
            if (u < nb) buf[u] = __ldg(&g_sp4[t + u]);
#pragma unroll
        for (int u = 0; u < CBATCH; u++) {
            if (u >= nb) continue;
            const float4 s = buf[u];
            const int j = __float_as_int(s.z);
            if (j == i) continue;
            const float sqj = __fadd_rn(__fmul_rn(s.x, s.x), __fmul_rn(s.y, s.y));
            const float dot = __fadd_rn(__fmul_rn(mx, s.x), __fmul_rn(my, s.y));
            const float d2  = __fadd_rn(__fadd_rn(sqi, sqj), __fmul_rn(-2.0f, dot));
            if (lexless(d2, j, wd, wj)) {
#pragma unroll
                for (int k = 0; k < KNN_K; k++) if (k == ws) { dd[k] = d2; jj[k] = j; }
                wd = dd[0]; wj = jj[0]; ws = 0;
#pragma unroll
                for (int k = 1; k < KNN_K; k++)
                    if (lexless(wd, wj, dd[k], jj[k])) { wd = dd[k]; wj = jj[k]; ws = k; }
            }
        }
        t += nb;
    }
}

__global__ void __launch_bounds__(64) knn_search(int* __restrict__ idx_out) {
    __shared__ int2 srange[NCELLS];
    for (int t = threadIdx.x; t < NCELLS; t += 64)
        srange[t] = g_range[t];
    __syncthreads();

    const int p = blockIdx.x * 64 + threadIdx.x;
    if (p >= N_SPOTS) return;
    const float4 me = g_sp4[p];
    const int i = __float_as_int(me.z);
    const float sqi = __fadd_rn(__fmul_rn(me.x, me.x), __fmul_rn(me.y, me.y));
    const int cx = cell_x(me.x), cy = cell_x(me.y);

    float dd[KNN_K]; int jj[KNN_K];
#pragma unroll
    for (int k = 0; k < KNN_K; k++) { dd[k] = INF_F; jj[k] = 0x7fffffff; }
    float wd = INF_F; int wj = 0x7fffffff; int ws = 0;

    for (int R = 0; R <= GRID_D; R++) {
        if (R >= 2) {
            const float b = (float)(R - 1) * CSZ;
            if (wd + SLACK < b * b) break;
        }
        const int x0 = max(0, cx - R), x1 = min(GRID_D - 1, cx + R);
        const int y0 = max(0, cy - R), y1 = min(GRID_D - 1, cy + R);
        for (int yy = y0; yy <= y1; yy++) {
            if (yy == cy - R || yy == cy + R) {
                proc_span(srange, yy * GRID_D + x0, yy * GRID_D + x1,
                          i, me.x, me.y, sqi, dd, jj, wd, wj, ws);
            } else {
                if (cx - R >= 0)
                    proc_span(srange, yy * GRID_D + cx - R, yy * GRID_D + cx - R,
                              i, me.x, me.y, sqi, dd, jj, wd, wj, ws);
                if (cx + R < GRID_D)
                    proc_span(srange, yy * GRID_D + cx + R, yy * GRID_D + cx + R,
                              i, me.x, me.y, sqi, dd, jj, wd, wj, ws);
            }
        }
    }
#pragma unroll
    for (int k = 0; k < KNN_K; k++) idx_out[i * KNN_K + k] = jj[k];
}

// --------------------------- aggregation (+ z bf16 split) ----------------------
__global__ void agg_kernel(const float* __restrict__ x,
                           const float* __restrict__ xn,
                           float* __restrict__ z_out,
                           float* __restrict__ hr_out) {
    const int i   = blockIdx.x;
    const int tid = threadIdx.x;          // 0..127
    const int lane = tid & 31, wrp = tid >> 5;

    __shared__ int   nb[KNN_K];
    __shared__ float red[4][KNN_K];
    __shared__ float neg_mean[KNN_K];

    if (tid < KNN_K) nb[tid] = g_idx[i * KNN_K + tid];
    __syncthreads();

    const float xi = x[(size_t)i * D_LAT + tid];
    float xv[KNN_K];
    float fd[KNN_K];
#pragma unroll
    for (int k = 0; k < KNN_K; k++) {
        const float v = x[(size_t)nb[k] * D_LAT + tid];
        xv[k] = v;
        const float d = v - xi;
        fd[k] = d * d;
    }
#pragma unroll
    for (int k = 0; k < KNN_K; k++) {
        float v = fd[k];
#pragma unroll
        for (int o = 16; o > 0; o >>= 1) v += __shfl_xor_sync(0xffffffffu, v, o);
        if (lane == 0) red[wrp][k] = v;
    }
    __syncthreads();
    if (tid < KNN_K) {
        const float s = red[0][tid] + red[1][tid] + red[2][tid] + red[3][tid];
        neg_mean[tid] = -(s * (1.0f / 128.0f));
    }
    __syncthreads();

    float m = neg_mean[0];
#pragma unroll
    for (int k = 1; k < KNN_K; k++) m = fmaxf(m, neg_mean[k]);
    float e[KNN_K], se = 0.0f;
#pragma unroll
    for (int k = 0; k < KNN_K; k++) { e[k] = expf(neg_mean[k] - m); se += e[k]; }
    float w[KNN_K];
#pragma unroll
    for (int k = 0; k < KNN_K; k++) w[k] = e[k] / se;

    float acc = 0.0f;
#pragma unroll
    for (int k = 0; k < KNN_K; k++) acc = __fmaf_rn(w[k], xv[k], acc);
    z_out[(size_t)i * D_LAT + tid] = acc;

    // bf16 hi/lo split of z, packed per k-pair (even lane packs tid & tid+1)
    const float accn = __shfl_down_sync(0xffffffffu, acc, 1);
    if ((tid & 1) == 0) {
        __nv_bfloat16 h0, l0, h1, l1;
        split_bf(acc,  h0, l0);
        split_bf(accn, h1, l1);
        g_zh[(size_t)i * 64 + (tid >> 1)] = pack2(h0, h1);
        g_zl[(size_t)i * 64 + (tid >> 1)] = pack2(l0, l1);
    }

#pragma unroll
    for (int s = 0; s < SCALE; s++) {
        float a = 0.0f;
#pragma unroll
        for (int k = 0; k < KNN_K; k++)
            a = __fmaf_rn(w[k], xn[((size_t)s * N_SPOTS + nb[k]) * D_LAT + tid], a);
        hr_out[(size_t)i * (SCALE * D_LAT) + s * D_LAT + tid] = a;
    }
}

// --------------------------- W bf16 split (kpair-major) ------------------------
__global__ void split_w(const float* __restrict__ W) {
    const int idx = blockIdx.x * 256 + threadIdx.x;     // kp * D_IN + n
    if (idx >= 64 * D_IN) return;
    const int kp = idx / D_IN, n = idx - kp * D_IN;
    const float v0 = W[(size_t)(2 * kp)     * D_IN + n];
    const float v1 = W[(size_t)(2 * kp + 1) * D_IN + n];
    __nv_bfloat16 h0, l0, h1, l1;
    split_bf(v0, h0, l0);
    split_bf(v1, h1, l1);
    g_bh[idx] = pack2(h0, h1);
    g_bl[idx] = pack2(l0, l1);
}

// --------------------------- Gram: G = Z^T Z, s = colsum(Z) --------------------
#define GRAM_BLOCKS 80
__global__ void __launch_bounds__(256) gram_kernel(const float* __restrict__ z) {
    __shared__ float zrow[D_LAT];
    const int tid = threadIdx.x;
    const int i_own = tid >> 1;
    const int jb    = (tid & 1) * 64;

    float acc[64];
#pragma unroll
    for (int q = 0; q < 64; q++) acc[q] = 0.0f;
    float s_loc = 0.0f;

    for (int m = blockIdx.x; m < N_SPOTS; m += GRAM_BLOCKS) {
        if (tid < D_LAT) zrow[tid] = z[(size_t)m * D_LAT + tid];
        __syncthreads();
        const float zi = zrow[i_own];
#pragma unroll
        for (int q = 0; q < 64; q++) acc[q] = __fmaf_rn(zi, zrow[jb + q], acc[q]);
        if (tid < D_LAT) s_loc += zrow[tid];
        __syncthreads();
    }
#pragma unroll
    for (int q = 0; q < 64; q++) atomicAdd(&g_G[i_own * D_LAT + jb + q], acc[q]);
    if (tid < D_LAT) atomicAdd(&g_s[tid], s_loc);
}

// --------------------------- BN stats from Gram --------------------------------
__global__ void __launch_bounds__(256) stats_kernel(const float* __restrict__ W,
                                                    const float* __restrict__ bias) {
    __shared__ float Gs[D_LAT][65];
    __shared__ float ws[8][D_LAT];
    __shared__ float ss[D_LAT];

    const int tid = threadIdx.x;
    const int wrp = tid >> 5, lane = tid & 31;
    const int c0 = blockIdx.x * 8;
    const int c  = c0 + wrp;

    for (int idx = tid; idx < 8 * D_LAT; idx += 256) {
        const int cc = idx & 7, i = idx >> 3;
        ws[cc][i] = W[(size_t)i * D_IN + c0 + cc];
    }
    if (tid < D_LAT) ss[tid] = g_s[tid];

    float tpart[4] = {0.0f, 0.0f, 0.0f, 0.0f};
    for (int half = 0; half < 2; half++) {
        __syncthreads();
        for (int idx = tid; idx < D_LAT * 64; idx += 256) {
            const int i = idx >> 6, jj = idx & 63;
            Gs[i][jj] = g_G[i * D_LAT + half * 64 + jj];
        }
        __syncthreads();
#pragma unroll
        for (int ii = 0; ii < 4; ii++) {
            const int i = lane + ii * 32;
            float t = tpart[ii];
            const float* wr = &ws[wrp][half * 64];
#pragma unroll
            for (int jj = 0; jj < 64; jj++) t = __fmaf_rn(Gs[i][jj], wr[jj], t);
            tpart[ii] = t;
        }
    }

    float u = 0.0f, sw = 0.0f;
#pragma unroll
    for (int ii = 0; ii < 4; ii++) {
        const int i = lane + ii * 32;
        const float wi = ws[wrp][i];
        u  = __fmaf_rn(wi, tpart[ii], u);
        sw = __fmaf_rn(ss[i], wi, sw);
    }
#pragma unroll
    for (int o = 16; o > 0; o >>= 1) {
        u  += __shfl_xor_sync(0xffffffffu, u, o);
        sw += __shfl_xor_sync(0xffffffffu, sw, o);
    }
    if (lane == 0) {
        const float b   = bias[c];
        const float mu  = sw * (1.0f / (float)N_SPOTS) + b;
        const float eh2 = (u + 2.0f * b * sw) * (1.0f / (float)N_SPOTS) + b * b;
        const float var = eh2 - mu * mu;
        g_mu[c] = mu;
        g_rs[c] = 1.0f / sqrtf(var + BN_EPS);
    }
}

// ----------------- GEMM: decoupled hybrid tensor(bf16x3) + FFMA(fp32) ----------
// de_feat = ELU(BN(z @ W + b)) [10000 x 3000], K=128. Per CTA: 128 rows x 128 cols.
//   warps 0-3: cols [tcol0, tcol0+64)  — legacy mma bf16 3-split (R9 math)
//   warps 4-7: cols [tcol0+64, +128)   — exact fp32 FFMA
// Families are FULLY decoupled: own smem buffers, own loaders, own named barrier
// (bar.sync 1 vs 2). No block-wide sync -> pipes overlap. Last x-tile: FFMA
// family inactive; tensor epilogue col-guard covers the 2944..2999 remainder.

__device__ __forceinline__ void mma_bf16(float* d, const uint32_t* a, const uint32_t* b) {
    asm volatile(
        "mma.sync.aligned.m16n8k16.row.col.f32.bf16.bf16.f32 "
        "{%0,%1,%2,%3}, {%4,%5,%6,%7}, {%8,%9}, {%0,%1,%2,%3};"
        : "+f"(d[0]), "+f"(d[1]), "+f"(d[2]), "+f"(d[3])
        : "r"(a[0]), "r"(a[1]), "r"(a[2]), "r"(a[3]), "r"(b[0]), "r"(b[1]));
}
#define BARRIER_T() asm volatile("bar.sync 1, 128;" ::: "memory")
#define BARRIER_F() asm volatile("bar.sync 2, 128;" ::: "memory")

#define ASTR 20    // uint32 per A row: words 0..7 hi (kpairs), 8..15 lo, 4 pad
#define BSTR 72    // uint32 per B kpair row: 64 n + 8 pad
#define AFS  132   // floats per Af k-row (128 + 4 pad)
#define BFS  68    // floats per Bf k-row (64 + 4 pad)

// dynamic smem offsets (bytes)
#define OFF_AS 0                           // [2][128][ASTR] u32 = 20480
#define OFF_BS 20480                       // [2][16][BSTR]  u32 = 9216
#define OFF_AF 29696                       // [2][16][AFS]   f32 = 16896
#define OFF_BF 46592                       // [2][16][BFS]   f32 = 8704
#define GEMM_SMEM 55296

__global__ void __launch_bounds__(256) gemm_kernel(const float* __restrict__ z,
                                                   const float* __restrict__ W,
                                                   const float* __restrict__ bias,
                                                   const float* __restrict__ gamma,
                                                   const float* __restrict__ beta,
                                                   float* __restrict__ de_out) {
    extern __shared__ char sm[];
    uint32_t* As = (uint32_t*)(sm + OFF_AS);
    uint32_t* Bs = (uint32_t*)(sm + OFF_BS);
    float*    Af = (float*)(sm + OFF_AF);
    float*    Bf = (float*)(sm + OFF_BF);
#define ASx(buf, r, w)  As[((buf) * 128 + (r)) * ASTR + (w)]
#define BSx(buf, kr, n) Bs[((buf) * 16 + (kr)) * BSTR + (n)]
#define AFx(buf, k, m)  Af[((buf) * 16 + (k)) * AFS + (m)]
#define BFx(buf, k, n)  Bf[((buf) * 16 + (k)) * BFS + (n)]

    const int tid  = threadIdx.x;
    const int bm   = blockIdx.y * 128;
    const int tcol0 = blockIdx.x * 128;
    const int fcol0 = tcol0 + 64;

    if (tid < 128) {
        // ================= tensor family (warps 0-3, cols tcol0..+63) =========
        const int wid  = tid >> 5;
        const int lane = tid & 31;
        const int tg   = lane & 3;
        const int gp   = lane >> 2;
        const int m0w  = wid * 32;

        const int row  = tid;                       // A row within tile
        const int arow = min(bm + row, N_SPOTS - 1);
        const int bkr  = tid >> 4;                  // B kpair row (0..7)
        const int bc4  = (tid & 15) * 4;            // B col (0..60)
        const int bcol = min(tcol0 + bc4, D_IN - 4);
        const uint32_t* zh_row = g_zh + (size_t)arow * 64;
        const uint32_t* zl_row = g_zl + (size_t)arow * 64;

        uint4 rah0, rah1, ral0, ral1, rbh, rbl;
#define T_LOADS(kp0)                                                     \
        {                                                                \
            rah0 = *(const uint4*)&zh_row[(kp0)];                        \
            rah1 = *(const uint4*)&zh_row[(kp0) + 4];                    \
            ral0 = *(const uint4*)&zl_row[(kp0)];                        \
            ral1 = *(const uint4*)&zl_row[(kp0) + 4];                    \
            rbh  = *(const uint4*)&g_bh[(size_t)((kp0) + bkr) * D_IN + bcol]; \
            rbl  = *(const uint4*)&g_bl[(size_t)((kp0) + bkr) * D_IN + bcol]; \
        }
#define T_STORES(buf)                                                    \
        {                                                                \
            *(uint4*)&ASx(buf, row, 0)  = rah0;                          \
            *(uint4*)&ASx(buf, row, 4)  = rah1;                          \
            *(uint4*)&ASx(buf, row, 8)  = ral0;                          \
            *(uint4*)&ASx(buf, row, 12) = ral1;                          \
            *(uint4*)&BSx(buf, bkr, bc4)     = rbh;                      \
            *(uint4*)&BSx(buf, 8 + bkr, bc4) = rbl;                      \
        }

        float acc[2][8][4];
#pragma unroll
        for (int mt = 0; mt < 2; mt++)
#pragma unroll
            for (int nt = 0; nt < 8; nt++)
#pragma unroll
                for (int q = 0; q < 4; q++) acc[mt][nt][q] = 0.0f;

        T_LOADS(0);
        T_STORES(0);
        BARRIER_T();

#pragma unroll 1
        for (int s = 0; s < 8; s++) {
            if (s < 7) T_LOADS((s + 1) * 8);
            const int cur = s & 1;

            uint32_t ah[2][4], al[2][4];
#pragma unroll
            for (int mt = 0; mt < 2; mt++) {
                const int mr = m0w + mt * 16;
                ah[mt][0] = ASx(cur, mr + gp,     tg);
                ah[mt][1] = ASx(cur, mr + gp + 8, tg);
                ah[mt][2] = ASx(cur, mr + gp,     tg + 4);
                ah[mt][3] = ASx(cur, mr + gp + 8, tg + 4);
                al[mt][0] = ASx(cur, mr + gp,     8 + tg);
                al[mt][1] = ASx(cur, mr + gp + 8, 8 + tg);
                al[mt][2] = ASx(cur, mr + gp,     8 + tg + 4);
                al[mt][3] = ASx(cur, mr + gp + 8, 8 + tg + 4);
            }
#pragma unroll
            for (int nt = 0; nt < 8; nt++) {
                const int nc = nt * 8 + gp;
                uint32_t bh[2] = { BSx(cur, tg, nc),     BSx(cur, tg + 4, nc) };
                uint32_t bl[2] = { BSx(cur, 8 + tg, nc), BSx(cur, 8 + tg + 4, nc) };
#pragma unroll
                for (int mt = 0; mt < 2; mt++) {
                    mma_bf16(acc[mt][nt], ah[mt], bh);
                    mma_bf16(acc[mt][nt], ah[mt], bl);
                    mma_bf16(acc[mt][nt], al[mt], bh);
                }
            }
            if (s < 7) {
                T_STORES((s + 1) & 1);
                BARRIER_T();
            }
        }

        // epilogue: bias + BN + ELU
#pragma unroll
        for (int nt = 0; nt < 8; nt++) {
            const int col = tcol0 + nt * 8 + tg * 2;
            if (col >= D_IN) continue;
            const float bia0 = __ldg(&bias[col]),  bia1 = __ldg(&bias[col + 1]);
            const float mu0  = g_mu[col],          mu1  = g_mu[col + 1];
            const float rs0  = g_rs[col],          rs1  = g_rs[col + 1];
            const float ga0  = __ldg(&gamma[col]), ga1  = __ldg(&gamma[col + 1]);
            const float be0  = __ldg(&beta[col]),  be1  = __ldg(&beta[col + 1]);
#pragma unroll
            for (int mt = 0; mt < 2; mt++) {
#pragma unroll
                for (int hf = 0; hf < 2; hf++) {
                    const int orow = bm + m0w + mt * 16 + gp + hf * 8;
                    if (orow >= N_SPOTS) continue;
                    const float h0 = acc[mt][nt][hf * 2 + 0] + bia0;
                    const float h1 = acc[mt][nt][hf * 2 + 1] + bia1;
                    float y0 = (h0 - mu0) * rs0 * ga0 + be0;
                    float y1 = (h1 - mu1) * rs1 * ga1 + be1;
                    y0 = (y0 > 0.0f) ? y0 : expm1f(y0);
                    y1 = (y1 > 0.0f) ? y1 : expm1f(y1);
                    *(float2*)&de_out[(size_t)orow * D_IN + col] = make_float2(y0, y1);
                }
            }
        }
    } else {
        // ================= FFMA family (warps 4-7, cols fcol0..+63) ===========
        if (fcol0 + 64 > D_IN) return;      // last x-tile: inactive (all 4 warps)
        const int ft = tid - 128;           // 0..127
        const int tm = ft & 15;             // 16 row groups of 8
        const int tn = ft >> 4;             // 8 col groups of 8

        const int arow = min(bm + ft, N_SPOTS - 1);
        // Bf loader: 256 items = 16 k-rows x 16 quad-cols; idx0 = ft, idx1 = ft+128
        const int bk   = ft >> 4;           // k row 0..7
        const int bq   = ft & 15;           // quad col 0..15
        const int bk1  = (ft + 128) >> 4;   // k row 8..15
        const int bq1  = (ft + 128) & 15;   // quad col 0..15

        float4 rz[4], rw0, rw1;
#define F_LOADS(kslab)                                                   \
        {                                                                \
            rz[0] = *(const float4*)&z[(size_t)arow * D_LAT + (kslab) + 0];  \
            rz[1] = *(const float4*)&z[(size_t)arow * D_LAT + (kslab) + 4];  \
            rz[2] = *(const float4*)&z[(size_t)arow * D_LAT + (kslab) + 8];  \
            rz[3] = *(const float4*)&z[(size_t)arow * D_LAT + (kslab) + 12]; \
            rw0 = *(const float4*)&W[(size_t)((kslab) + bk)  * D_IN + fcol0 + bq  * 4]; \
            rw1 = *(const float4*)&W[(size_t)((kslab) + bk1) * D_IN + fcol0 + bq1 * 4]; \
        }
#define F_STORES(buf)                                                    \
        {                                                                \
            _Pragma("unroll")                                            \
            for (int j = 0; j < 4; j++) {                                \
                AFx(buf, j * 4 + 0, ft) = rz[j].x;                       \
                AFx(buf, j * 4 + 1, ft) = rz[j].y;                       \
                AFx(buf, j * 4 + 2, ft) = rz[j].z;                       \
                AFx(buf, j * 4 + 3, ft) = rz[j].w;                       \
            }                                                            \
            *(float4*)&BFx(buf, bk,  bq  * 4) = rw0;                     \
            *(float4*)&BFx(buf, bk1, bq1 * 4) = rw1;                     \
        }

        float facc[8][8];
#pragma unroll
        for (int p = 0; p < 8; p++)
#pragma unroll
            for (int q = 0; q < 8; q++) facc[p][q] = 0.0f;

        F_LOADS(0);
        F_STORES(0);
        BARRIER_F();

#pragma unroll 1
        for (int s = 0; s < 8; s++) {
            if (s < 7) F_LOADS((s + 1) * 16);
            const int cur = s & 1;
#pragma unroll
            for (int kk = 0; kk < 16; kk++) {
                float a[8], b[8];
                *(float4*)&a[0] = *(const float4*)&AFx(cur, kk, tm * 8);
                *(float4*)&a[4] = *(const float4*)&AFx(cur, kk, tm * 8 + 4);
                *(float4*)&b[0] = *(const float4*)&BFx(cur, kk, tn * 8);
                *(float4*)&b[4] = *(const float4*)&BFx(cur, kk, tn * 8 + 4);
#pragma unroll
                for (int p = 0; p < 8; p++)
#pragma unroll
                    for (int q = 0; q < 8; q++)
                        facc[p][q] = __fmaf_rn(a[p], b[q], facc[p][q]);
            }
            if (s < 7) {
                F_STORES((s + 1) & 1);
                BARRIER_F();
            }
        }

        // epilogue: bias + BN + ELU (cols fcol0 + tn*8 .. +7, all < D_IN here)
        float bia[8], mu[8], rs[8], ga[8], be[8];
#pragma unroll
        for (int q = 0; q < 8; q++) {
            const int col = fcol0 + tn * 8 + q;
            bia[q] = __ldg(&bias[col]);
            mu[q]  = g_mu[col];
            rs[q]  = g_rs[col];
            ga[q]  = __ldg(&gamma[col]);
            be[q]  = __ldg(&beta[col]);
        }
#pragma unroll
        for (int p = 0; p < 8; p++) {
            const int orow = bm + tm * 8 + p;
            if (orow >= N_SPOTS) continue;
            float y[8];
#pragma unroll
            for (int q = 0; q < 8; q++) {
                const float h = facc[p][q] + bia[q];
                float v = (h - mu[q]) * rs[q] * ga[q] + be[q];
                y[q] = (v > 0.0f) ? v : expm1f(v);
            }
            float* dst = de_out + (size_t)orow * D_IN + fcol0 + tn * 8;
            *(float4*)dst       = *(float4*)&y[0];
            *(float4*)(dst + 4) = *(float4*)&y[4];
        }
    }
}

// ------------------------------- launch ----------------------------------------
extern "C" void kernel_launch(void* const* d_in, const int* in_sizes, int n_in,
                              void* d_out, int out_size) {
    const float* x     = (const float*)d_in[0];   // [10000,128]
    const float* xn    = (const float*)d_in[1];   // [60000,128]
    const float* sp    = (const float*)d_in[2];   // [10000,2]
    const float* W     = (const float*)d_in[3];   // [128,3000]
    const float* bias  = (const float*)d_in[4];   // [3000]
    const float* gamma = (const float*)d_in[5];   // [3000]
    const float* beta  = (const float*)d_in[6];   // [3000]

    float* out = (float*)d_out;
    float* z_out  = out;                                   // [10000,128]
    float* de_out = out + (size_t)N_SPOTS * D_LAT;         // [10000,3000]
    float* hr_out = de_out + (size_t)N_SPOTS * D_IN;       // [10000,768]

    int* idx_ptr;   cudaGetSymbolAddress((void**)&idx_ptr, g_idx);

    cudaFuncSetAttribute(gemm_kernel, cudaFuncAttributeMaxDynamicSharedMemorySize, GEMM_SMEM);

    zero_scratch<<<(D_LAT * D_LAT + 255) / 256, 256>>>();
    knn_count  <<<(N_SPOTS + 255) / 256, 256>>>((const float2*)sp);
    knn_scan   <<<1, 32>>>();
    knn_scatter<<<(N_SPOTS + 255) / 256, 256>>>((const float2*)sp);
    split_w    <<<(64 * D_IN + 255) / 256, 256>>>(W);
    knn_search <<<(N_SPOTS + 63) / 64, 64>>>(idx_ptr);
    agg_kernel <<<N_SPOTS, 128>>>(x, xn, z_out, hr_out);
    gram_kernel<<<GRAM_BLOCKS, 256>>>(z_out);
    stats_kernel<<<D_IN / 8, 256>>>(W, bias);
    gemm_kernel<<<dim3((D_IN + 127) / 128, (N_SPOTS + 127) / 128), 256, GEMM_SMEM>>>(
        z_out, W, bias, gamma, beta, de_out);
}

// round 17
// speedup vs baseline: 1.0048x; 1.0048x over previous
#include <cuda_runtime.h>
#include <cuda_bf16.h>
#include <math.h>
#include <stdint.h>

// Problem constants (fixed shapes)
#define N_SPOTS 10000
#define D_LAT   128
#define D_IN    3000
#define KNN_K   10
#define SCALE   6
#define BN_EPS  1e-4f

// KNN grid
#define GRID_D  40
#define CSZ     2.5f
#define INV_CSZ 0.4f
#define NCELLS  (GRID_D * GRID_D)
#define SLACK   0.5f

#define INF_F __int_as_float(0x7f800000)

// ---------------- scratch (device globals; no allocation allowed) -------------
__device__ int    g_idx[N_SPOTS * KNN_K];
__device__ int    g_cnt[NCELLS];
__device__ int    g_cur[NCELLS];
__device__ __align__(8)  int2   g_range[NCELLS];      // (start, count)
__device__ __align__(16) float4 g_sp4[N_SPOTS];       // (x, y, idx-bits, 0)
__device__ __align__(16) float g_G[D_LAT * D_LAT];    // Z^T Z
__device__ __align__(16) float g_s[D_LAT];            // col-sum of Z
__device__ __align__(16) float g_mu[D_IN];
__device__ __align__(16) float g_rs[D_IN];
// pre-split bf16 hi/lo operands (packed bf16x2 per k-pair), kpair-major for W
__device__ __align__(16) uint32_t g_zh[(size_t)N_SPOTS * 64];   // [row][kp]
__device__ __align__(16) uint32_t g_zl[(size_t)N_SPOTS * 64];
__device__ __align__(16) uint32_t g_bh[(size_t)64 * D_IN];      // [kp][n]
__device__ __align__(16) uint32_t g_bl[(size_t)64 * D_IN];

// lexicographic (d2, idx) compare: matches jax.lax.top_k stable tie-break
__device__ __forceinline__ bool lexless(float d1, int j1, float d2, int j2) {
    return (d1 < d2) || (d1 == d2 && j1 < j2);
}

__device__ __forceinline__ int cell_x(float x) {
    int c = (int)(x * INV_CSZ);
    return min(GRID_D - 1, max(0, c));
}

__device__ __forceinline__ void split_bf(float v, __nv_bfloat16& h, __nv_bfloat16& l) {
    h = __float2bfloat16_rn(v);
    l = __float2bfloat16_rn(v - __bfloat162float(h));
}

__device__ __forceinline__ uint32_t pack2(__nv_bfloat16 a, __nv_bfloat16 b) {
    __nv_bfloat162 t; t.x = a; t.y = b;     // .x = low 16 bits = lower-k element
    return *reinterpret_cast<uint32_t*>(&t);
}

// --------------------------- zero all scratch (1 launch) ------------------------
__global__ void zero_scratch() {
    const int i = blockIdx.x * 256 + threadIdx.x;
    if (i < NCELLS) { g_cnt[i] = 0; g_cur[i] = 0; }
    if (i < D_LAT)  g_s[i] = 0.0f;
    if (i < D_LAT * D_LAT) g_G[i] = 0.0f;
}

// ----------------------------- KNN: build grid ---------------------------------
__global__ void knn_count(const float2* __restrict__ sp) {
    const int i = blockIdx.x * 256 + threadIdx.x;
    if (i >= N_SPOTS) return;
    const float2 s = sp[i];
    atomicAdd(&g_cnt[cell_x(s.y) * GRID_D + cell_x(s.x)], 1);
}

// single-warp exclusive scan over 1600 cells
__global__ void knn_scan() {
    const int lane = threadIdx.x;           // 32 threads
    const int CH = NCELLS / 32;             // 50
    const int base = lane * CH;
    int s = 0;
    for (int k = 0; k < CH; k++) s += g_cnt[base + k];
    int inc = s;
#pragma unroll
    for (int o = 1; o < 32; o <<= 1) {
        int v = __shfl_up_sync(0xffffffffu, inc, o);
        if (lane >= o) inc += v;
    }
    int run = inc - s;
    for (int k = 0; k < CH; k++) {
        const int c = g_cnt[base + k];
        g_range[base + k] = make_int2(run, c);
        run += c;
    }
}

__global__ void knn_scatter(const float2* __restrict__ sp) {
    const int i = blockIdx.x * 256 + threadIdx.x;
    if (i >= N_SPOTS) return;
    const float2 s = sp[i];
    const int c = cell_x(s.y) * GRID_D + cell_x(s.x);
    const int dst = g_range[c].x + atomicAdd(&g_cur[c], 1);
    g_sp4[dst] = make_float4(s.x, s.y, __int_as_float(i), 0.0f);
}

// ----------------------------- KNN: ring search --------------------------------
// d2 BIT-EXACT vs reference (XLA lowers the K=2 dot without fma):
//   sq = rn(rn(x*x) + rn(y*y));  dot = rn(rn(xi*xj) + rn(yi*yj))
//   d2 = rn(rn(sqi + sqj) - 2*dot)
#define CBATCH 8
__device__ __forceinline__ void proc_span(const int2* __restrict__ sr, int ca, int cb,
                                          int i, float mx, float my, float sqi,
                                          float* dd, int* jj,
                                          float& wd, int& wj, int& ws) {
    const int2 ra = sr[ca];
    const int2 rb = sr[cb];
    int t = ra.x;
    const int t1 = rb.x + rb.y;
    while (t < t1) {
        const int nb = min(t1 - t, CBATCH);
        float4 buf[CBATCH];
#pragma unroll
        for (int u = 0; u < CBATCH; u++)
            if (u < nb) buf[u] = __ldg(&g_sp4[t + u]);
#pragma unroll
        for (int u = 0; u < CBATCH; u++) {
            if (u >= nb) continue;
            const float4 s = buf[u];
            const int j = __float_as_int(s.z);
            if (j == i) continue;
            const float sqj = __fadd_rn(__fmul_rn(s.x, s.x), __fmul_rn(s.y, s.y));
            const float dot = __fadd_rn(__fmul_rn(mx, s.x), __fmul_rn(my, s.y));
            const float d2  = __fadd_rn(__fadd_rn(sqi, sqj), __fmul_rn(-2.0f, dot));
            if (lexless(d2, j, wd, wj)) {
#pragma unroll
                for (int k = 0; k < KNN_K; k++) if (k == ws) { dd[k] = d2; jj[k] = j; }
                wd = dd[0]; wj = jj[0]; ws = 0;
#pragma unroll
                for (int k = 1; k < KNN_K; k++)
                    if (lexless(wd, wj, dd[k], jj[k])) { wd = dd[k]; wj = jj[k]; ws = k; }
            }
        }
        t += nb;
    }
}

__global__ void __launch_bounds__(64) knn_search(int* __restrict__ idx_out) {
    __shared__ int2 srange[NCELLS];
    for (int t = threadIdx.x; t < NCELLS; t += 64)
        srange[t] = g_range[t];
    __syncthreads();

    const int p = blockIdx.x * 64 + threadIdx.x;
    if (p >= N_SPOTS) return;
    const float4 me = g_sp4[p];
    const int i = __float_as_int(me.z);
    const float sqi = __fadd_rn(__fmul_rn(me.x, me.x), __fmul_rn(me.y, me.y));
    const int cx = cell_x(me.x), cy = cell_x(me.y);

    float dd[KNN_K]; int jj[KNN_K];
#pragma unroll
    for (int k = 0; k < KNN_K; k++) { dd[k] = INF_F; jj[k] = 0x7fffffff; }
    float wd = INF_F; int wj = 0x7fffffff; int ws = 0;

    for (int R = 0; R <= GRID_D; R++) {
        if (R >= 2) {
            const float b = (float)(R - 1) * CSZ;
            if (wd + SLACK < b * b) break;
        }
        const int x0 = max(0, cx - R), x1 = min(GRID_D - 1, cx + R);
        const int y0 = max(0, cy - R), y1 = min(GRID_D - 1, cy + R);
        for (int yy = y0; yy <= y1; yy++) {
            if (yy == cy - R || yy == cy + R) {
                proc_span(srange, yy * GRID_D + x0, yy * GRID_D + x1,
                          i, me.x, me.y, sqi, dd, jj, wd, wj, ws);
            } else {
                if (cx - R >= 0)
                    proc_span(srange, yy * GRID_D + cx - R, yy * GRID_D + cx - R,
                              i, me.x, me.y, sqi, dd, jj, wd, wj, ws);
                if (cx + R < GRID_D)
                    proc_span(srange, yy * GRID_D + cx + R, yy * GRID_D + cx + R,
                              i, me.x, me.y, sqi, dd, jj, wd, wj, ws);
            }
        }
    }
#pragma unroll
    for (int k = 0; k < KNN_K; k++) idx_out[i * KNN_K + k] = jj[k];
}

// --------------------------- aggregation (+ z bf16 split) ----------------------
__global__ void agg_kernel(const float* __restrict__ x,
                           const float* __restrict__ xn,
                           float* __restrict__ z_out,
                           float* __restrict__ hr_out) {
    const int i   = blockIdx.x;
    const int tid = threadIdx.x;          // 0..127
    const int lane = tid & 31, wrp = tid >> 5;

    __shared__ int   nb[KNN_K];
    __shared__ float red[4][KNN_K];
    __shared__ float neg_mean[KNN_K];

    if (tid < KNN_K) nb[tid] = g_idx[i * KNN_K + tid];
    __syncthreads();

    const float xi = x[(size_t)i * D_LAT + tid];
    float xv[KNN_K];
    float fd[KNN_K];
#pragma unroll
    for (int k = 0; k < KNN_K; k++) {
        const float v = x[(size_t)nb[k] * D_LAT + tid];
        xv[k] = v;
        const float d = v - xi;
        fd[k] = d * d;
    }
#pragma unroll
    for (int k = 0; k < KNN_K; k++) {
        float v = fd[k];
#pragma unroll
        for (int o = 16; o > 0; o >>= 1) v += __shfl_xor_sync(0xffffffffu, v, o);
        if (lane == 0) red[wrp][k] = v;
    }
    __syncthreads();
    if (tid < KNN_K) {
        const float s = red[0][tid] + red[1][tid] + red[2][tid] + red[3][tid];
        neg_mean[tid] = -(s * (1.0f / 128.0f));
    }
    __syncthreads();

    float m = neg_mean[0];
#pragma unroll
    for (int k = 1; k < KNN_K; k++) m = fmaxf(m, neg_mean[k]);
    float e[KNN_K], se = 0.0f;
#pragma unroll
    for (int k = 0; k < KNN_K; k++) { e[k] = expf(neg_mean[k] - m); se += e[k]; }
    float w[KNN_K];
#pragma unroll
    for (int k = 0; k < KNN_K; k++) w[k] = e[k] / se;

    float acc = 0.0f;
#pragma unroll
    for (int k = 0; k < KNN_K; k++) acc = __fmaf_rn(w[k], xv[k], acc);
    z_out[(size_t)i * D_LAT + tid] = acc;

    // bf16 hi/lo split of z, packed per k-pair (even lane packs tid & tid+1)
    const float accn = __shfl_down_sync(0xffffffffu, acc, 1);
    if ((tid & 1) == 0) {
        __nv_bfloat16 h0, l0, h1, l1;
        split_bf(acc,  h0, l0);
        split_bf(accn, h1, l1);
        g_zh[(size_t)i * 64 + (tid >> 1)] = pack2(h0, h1);
        g_zl[(size_t)i * 64 + (tid >> 1)] = pack2(l0, l1);
    }

#pragma unroll
    for (int s = 0; s < SCALE; s++) {
        float a = 0.0f;
#pragma unroll
        for (int k = 0; k < KNN_K; k++)
            a = __fmaf_rn(w[k], xn[((size_t)s * N_SPOTS + nb[k]) * D_LAT + tid], a);
        hr_out[(size_t)i * (SCALE * D_LAT) + s * D_LAT + tid] = a;
    }
}

// --------------------------- W bf16 split (kpair-major) ------------------------
__global__ void split_w(const float* __restrict__ W) {
    const int idx = blockIdx.x * 256 + threadIdx.x;     // kp * D_IN + n
    if (idx >= 64 * D_IN) return;
    const int kp = idx / D_IN, n = idx - kp * D_IN;
    const float v0 = W[(size_t)(2 * kp)     * D_IN + n];
    const float v1 = W[(size_t)(2 * kp + 1) * D_IN + n];
    __nv_bfloat16 h0, l0, h1, l1;
    split_bf(v0, h0, l0);
    split_bf(v1, h1, l1);
    g_bh[idx] = pack2(h0, h1);
    g_bl[idx] = pack2(l0, l1);
}

// --------------------------- Gram: G = Z^T Z, s = colsum(Z) --------------------
#define GRAM_BLOCKS 80
__global__ void __launch_bounds__(256) gram_kernel(const float* __restrict__ z) {
    __shared__ float zrow[D_LAT];
    const int tid = threadIdx.x;
    const int i_own = tid >> 1;
    const int jb    = (tid & 1) * 64;

    float acc[64];
#pragma unroll
    for (int q = 0; q < 64; q++) acc[q] = 0.0f;
    float s_loc = 0.0f;

    for (int m = blockIdx.x; m < N_SPOTS; m += GRAM_BLOCKS) {
        if (tid < D_LAT) zrow[tid] = z[(size_t)m * D_LAT + tid];
        __syncthreads();
        const float zi = zrow[i_own];
#pragma unroll
        for (int q = 0; q < 64; q++) acc[q] = __fmaf_rn(zi, zrow[jb + q], acc[q]);
        if (tid < D_LAT) s_loc += zrow[tid];
        __syncthreads();
    }
#pragma unroll
    for (int q = 0; q < 64; q++) atomicAdd(&g_G[i_own * D_LAT + jb + q], acc[q]);
    if (tid < D_LAT) atomicAdd(&g_s[tid], s_loc);
}

// --------------------------- BN stats from Gram --------------------------------
__global__ void __launch_bounds__(256) stats_kernel(const float* __restrict__ W,
                                                    const float* __restrict__ bias) {
    __shared__ float Gs[D_LAT][65];
    __shared__ float ws[8][D_LAT];
    __shared__ float ss[D_LAT];

    const int tid = threadIdx.x;
    const int wrp = tid >> 5, lane = tid & 31;
    const int c0 = blockIdx.x * 8;
    const int c  = c0 + wrp;

    for (int idx = tid; idx < 8 * D_LAT; idx += 256) {
        const int cc = idx & 7, i = idx >> 3;
        ws[cc][i] = W[(size_t)i * D_IN + c0 + cc];
    }
    if (tid < D_LAT) ss[tid] = g_s[tid];

    float tpart[4] = {0.0f, 0.0f, 0.0f, 0.0f};
    for (int half = 0; half < 2; half++) {
        __syncthreads();
        for (int idx = tid; idx < D_LAT * 64; idx += 256) {
            const int i = idx >> 6, jj = idx & 63;
            Gs[i][jj] = g_G[i * D_LAT + half * 64 + jj];
        }
        __syncthreads();
#pragma unroll
        for (int ii = 0; ii < 4; ii++) {
            const int i = lane + ii * 32;
            float t = tpart[ii];
            const float* wr = &ws[wrp][half * 64];
#pragma unroll
            for (int jj = 0; jj < 64; jj++) t = __fmaf_rn(Gs[i][jj], wr[jj], t);
            tpart[ii] = t;
        }
    }

    float u = 0.0f, sw = 0.0f;
#pragma unroll
    for (int ii = 0; ii < 4; ii++) {
        const int i = lane + ii * 32;
        const float wi = ws[wrp][i];
        u  = __fmaf_rn(wi, tpart[ii], u);
        sw = __fmaf_rn(ss[i], wi, sw);
    }
#pragma unroll
    for (int o = 16; o > 0; o >>= 1) {
        u  += __shfl_xor_sync(0xffffffffu, u, o);
        sw += __shfl_xor_sync(0xffffffffu, sw, o);
    }
    if (lane == 0) {
        const float b   = bias[c];
        const float mu  = sw * (1.0f / (float)N_SPOTS) + b;
        const float eh2 = (u + 2.0f * b * sw) * (1.0f / (float)N_SPOTS) + b * b;
        const float var = eh2 - mu * mu;
        g_mu[c] = mu;
        g_rs[c] = 1.0f / sqrtf(var + BN_EPS);
    }
}

// ----------------- GEMM: decoupled hybrid tensor(bf16x3) + FFMA(fp32) ----------
// de_feat = ELU(BN(z @ W + b)) [10000 x 3000], K=128. Per CTA: 128 rows x 128 cols.
//   warps 0-3: cols [tcol0, tcol0+64)  — legacy mma bf16 3-split (R9 math)
//   warps 4-7: cols [tcol0+64, +128)   — exact fp32 FFMA
// Families are FULLY decoupled: own smem buffers, own loaders, own named barrier
// (bar.sync 1 vs 2). No block-wide sync -> pipes overlap. Last x-tile: FFMA
// family inactive; tensor epilogue col-guard covers the 2944..2999 remainder.

__device__ __forceinline__ void mma_bf16(float* d, const uint32_t* a, const uint32_t* b) {
    asm volatile(
        "mma.sync.aligned.m16n8k16.row.col.f32.bf16.bf16.f32 "
        "{%0,%1,%2,%3}, {%4,%5,%6,%7}, {%8,%9}, {%0,%1,%2,%3};"
        : "+f"(d[0]), "+f"(d[1]), "+f"(d[2]), "+f"(d[3])
        : "r"(a[0]), "r"(a[1]), "r"(a[2]), "r"(a[3]), "r"(b[0]), "r"(b[1]));
}
#define BARRIER_T() asm volatile("bar.sync 1, 128;" ::: "memory")
#define BARRIER_F() asm volatile("bar.sync 2, 128;" ::: "memory")

#define ASTR 20    // uint32 per A row: words 0..7 hi (kpairs), 8..15 lo, 4 pad
#define BSTR 72    // uint32 per B kpair row: 64 n + 8 pad
#define AFS  132   // floats per Af k-row (128 + 4 pad)
#define BFS  68    // floats per Bf k-row (64 + 4 pad)

// dynamic smem offsets (bytes)
#define OFF_AS 0                           // [2][128][ASTR] u32 = 20480
#define OFF_BS 20480                       // [2][16][BSTR]  u32 = 9216
#define OFF_AF 29696                       // [2][16][AFS]   f32 = 16896
#define OFF_BF 46592                       // [2][16][BFS]   f32 = 8704
#define GEMM_SMEM 55296

__global__ void __launch_bounds__(256) gemm_kernel(const float* __restrict__ z,
                                                   const float* __restrict__ W,
                                                   const float* __restrict__ bias,
                                                   const float* __restrict__ gamma,
                                                   const float* __restrict__ beta,
                                                   float* __restrict__ de_out) {
    extern __shared__ char sm[];
    uint32_t* As = (uint32_t*)(sm + OFF_AS);
    uint32_t* Bs = (uint32_t*)(sm + OFF_BS);
    float*    Af = (float*)(sm + OFF_AF);
    float*    Bf = (float*)(sm + OFF_BF);
#define ASx(buf, r, w)  As[((buf) * 128 + (r)) * ASTR + (w)]
#define BSx(buf, kr, n) Bs[((buf) * 16 + (kr)) * BSTR + (n)]
#define AFx(buf, k, m)  Af[((buf) * 16 + (k)) * AFS + (m)]
#define BFx(buf, k, n)  Bf[((buf) * 16 + (k)) * BFS + (n)]

    const int tid  = threadIdx.x;
    const int bm   = blockIdx.y * 128;
    const int tcol0 = blockIdx.x * 128;
    const int fcol0 = tcol0 + 64;

    if (tid < 128) {
        // ================= tensor family (warps 0-3, cols tcol0..+63) =========
        const int wid  = tid >> 5;
        const int lane = tid & 31;
        const int tg   = lane & 3;
        const int gp   = lane >> 2;
        const int m0w  = wid * 32;

        const int row  = tid;                       // A row within tile
        const int arow = min(bm + row, N_SPOTS - 1);
        const int bkr  = tid >> 4;                  // B kpair row (0..7)
        const int bc4  = (tid & 15) * 4;            // B col (0..60)
        const int bcol = min(tcol0 + bc4, D_IN - 4);
        const uint32_t* zh_row = g_zh + (size_t)arow * 64;
        const uint32_t* zl_row = g_zl + (size_t)arow * 64;

        uint4 rah0, rah1, ral0, ral1, rbh, rbl;
#define T_LOADS(kp0)                                                     \
        {                                                                \
            rah0 = *(const uint4*)&zh_row[(kp0)];                        \
            rah1 = *(const uint4*)&zh_row[(kp0) + 4];                    \
            ral0 = *(const uint4*)&zl_row[(kp0)];                        \
            ral1 = *(const uint4*)&zl_row[(kp0) + 4];                    \
            rbh  = *(const uint4*)&g_bh[(size_t)((kp0) + bkr) * D_IN + bcol]; \
            rbl  = *(const uint4*)&g_bl[(size_t)((kp0) + bkr) * D_IN + bcol]; \
        }
#define T_STORES(buf)                                                    \
        {                                                                \
            *(uint4*)&ASx(buf, row, 0)  = rah0;                          \
            *(uint4*)&ASx(buf, row, 4)  = rah1;                          \
            *(uint4*)&ASx(buf, row, 8)  = ral0;                          \
            *(uint4*)&ASx(buf, row, 12) = ral1;                          \
            *(uint4*)&BSx(buf, bkr, bc4)     = rbh;                      \
            *(uint4*)&BSx(buf, 8 + bkr, bc4) = rbl;                      \
        }

        float acc[2][8][4];
#pragma unroll
        for (int mt = 0; mt < 2; mt++)
#pragma unroll
            for (int nt = 0; nt < 8; nt++)
#pragma unroll
                for (int q = 0; q < 4; q++) acc[mt][nt][q] = 0.0f;

        T_LOADS(0);
        T_STORES(0);
        BARRIER_T();

#pragma unroll 1
        for (int s = 0; s < 8; s++) {
            if (s < 7) T_LOADS((s + 1) * 8);
            const int cur = s & 1;

            uint32_t ah[2][4], al[2][4];
#pragma unroll
            for (int mt = 0; mt < 2; mt++) {
                const int mr = m0w + mt * 16;
                ah[mt][0] = ASx(cur, mr + gp,     tg);
                ah[mt][1] = ASx(cur, mr + gp + 8, tg);
                ah[mt][2] = ASx(cur, mr + gp,     tg + 4);
                ah[mt][3] = ASx(cur, mr + gp + 8, tg + 4);
                al[mt][0] = ASx(cur, mr + gp,     8 + tg);
                al[mt][1] = ASx(cur, mr + gp + 8, 8 + tg);
                al[mt][2] = ASx(cur, mr + gp,     8 + tg + 4);
                al[mt][3] = ASx(cur, mr + gp + 8, 8 + tg + 4);
            }
#pragma unroll
            for (int nt = 0; nt < 8; nt++) {
                const int nc = nt * 8 + gp;
                uint32_t bh[2] = { BSx(cur, tg, nc),     BSx(cur, tg + 4, nc) };
                uint32_t bl[2] = { BSx(cur, 8 + tg, nc), BSx(cur, 8 + tg + 4, nc) };
#pragma unroll
                for (int mt = 0; mt < 2; mt++) {
                    mma_bf16(acc[mt][nt], ah[mt], bh);
                    mma_bf16(acc[mt][nt], ah[mt], bl);
                    mma_bf16(acc[mt][nt], al[mt], bh);
                }
            }
            if (s < 7) {
                T_STORES((s + 1) & 1);
                BARRIER_T();
            }
        }

        // epilogue: bias + BN + ELU
#pragma unroll
        for (int nt = 0; nt < 8; nt++) {
            const int col = tcol0 + nt * 8 + tg * 2;
            if (col >= D_IN) continue;
            const float bia0 = __ldg(&bias[col]),  bia1 = __ldg(&bias[col + 1]);
            const float mu0  = g_mu[col],          mu1  = g_mu[col + 1];
            const float rs0  = g_rs[col],          rs1  = g_rs[col + 1];
            const float ga0  = __ldg(&gamma[col]), ga1  = __ldg(&gamma[col + 1]);
            const float be0  = __ldg(&beta[col]),  be1  = __ldg(&beta[col + 1]);
#pragma unroll
            for (int mt = 0; mt < 2; mt++) {
#pragma unroll
                for (int hf = 0; hf < 2; hf++) {
                    const int orow = bm + m0w + mt * 16 + gp + hf * 8;
                    if (orow >= N_SPOTS) continue;
                    const float h0 = acc[mt][nt][hf * 2 + 0] + bia0;
                    const float h1 = acc[mt][nt][hf * 2 + 1] + bia1;
                    float y0 = (h0 - mu0) * rs0 * ga0 + be0;
                    float y1 = (h1 - mu1) * rs1 * ga1 + be1;
                    y0 = (y0 > 0.0f) ? y0 : expm1f(y0);
                    y1 = (y1 > 0.0f) ? y1 : expm1f(y1);
                    *(float2*)&de_out[(size_t)orow * D_IN + col] = make_float2(y0, y1);
                }
            }
        }
    } else {
        // ================= FFMA family (warps 4-7, cols fcol0..+63) ===========
        if (fcol0 + 64 > D_IN) return;      // last x-tile: inactive (all 4 warps)
        const int ft = tid - 128;           // 0..127
        const int tm = ft & 15;             // 16 row groups of 8
        const int tn = ft >> 4;             // 8 col groups of 8

        const int arow = min(bm + ft, N_SPOTS - 1);
        // Bf loader: 256 items = 16 k-rows x 16 quad-cols; idx0 = ft, idx1 = ft+128
        const int bk   = ft >> 4;           // k row 0..7
        const int bq   = ft & 15;           // quad col 0..15
        const int bk1  = (ft + 128) >> 4;   // k row 8..15
        const int bq1  = (ft + 128) & 15;   // quad col 0..15

        float4 rz[4], rw0, rw1;
#define F_LOADS(kslab)                                                   \
        {                                                                \
            rz[0] = *(const float4*)&z[(size_t)arow * D_LAT + (kslab) + 0];  \
            rz[1] = *(const float4*)&z[(size_t)arow * D_LAT + (kslab) + 4];  \
            rz[2] = *(const float4*)&z[(size_t)arow * D_LAT + (kslab) + 8];  \
            rz[3] = *(const float4*)&z[(size_t)arow * D_LAT + (kslab) + 12]; \
            rw0 = *(const float4*)&W[(size_t)((kslab) + bk)  * D_IN + fcol0 + bq  * 4]; \
            rw1 = *(const float4*)&W[(size_t)((kslab) + bk1) * D_IN + fcol0 + bq1 * 4]; \
        }
#define F_STORES(buf)                                                    \
        {                                                                \
            _Pragma("unroll")                                            \
            for (int j = 0; j < 4; j++) {                                \
                AFx(buf, j * 4 + 0, ft) = rz[j].x;                       \
                AFx(buf, j * 4 + 1, ft) = rz[j].y;                       \
                AFx(buf, j * 4 + 2, ft) = rz[j].z;                       \
                AFx(buf, j * 4 + 3, ft) = rz[j].w;                       \
            }                                                            \
            *(float4*)&BFx(buf, bk,  bq  * 4) = rw0;                     \
            *(float4*)&BFx(buf, bk1, bq1 * 4) = rw1;                     \
        }

        float facc[8][8];
#pragma unroll
        for (int p = 0; p < 8; p++)
#pragma unroll
            for (int q = 0; q < 8; q++) facc[p][q] = 0.0f;

        F_LOADS(0);
        F_STORES(0);
        BARRIER_F();

#pragma unroll 1
        for (int s = 0; s < 8; s++) {
            if (s < 7) F_LOADS((s + 1) * 16);
            const int cur = s & 1;
#pragma unroll
            for (int kk = 0; kk < 16; kk++) {
                float a[8], b[8];
                *(float4*)&a[0] = *(const float4*)&AFx(cur, kk, tm * 8);
                *(float4*)&a[4] = *(const float4*)&AFx(cur, kk, tm * 8 + 4);
                *(float4*)&b[0] = *(const float4*)&BFx(cur, kk, tn * 8);
                *(float4*)&b[4] = *(const float4*)&BFx(cur, kk, tn * 8 + 4);
#pragma unroll
                for (int p = 0; p < 8; p++)
#pragma unroll
                    for (int q = 0; q < 8; q++)
                        facc[p][q] = __fmaf_rn(a[p], b[q], facc[p][q]);
            }
            if (s < 7) {
                F_STORES((s + 1) & 1);
                BARRIER_F();
            }
        }

        // epilogue: bias + BN + ELU (cols fcol0 + tn*8 .. +7, all < D_IN here)
        float bia[8], mu[8], rs[8], ga[8], be[8];
#pragma unroll
        for (int q = 0; q < 8; q++) {
            const int col = fcol0 + tn * 8 + q;
            bia[q] = __ldg(&bias[col]);
            mu[q]  = g_mu[col];
            rs[q]  = g_rs[col];
            ga[q]  = __ldg(&gamma[col]);
            be[q]  = __ldg(&beta[col]);
        }
#pragma unroll
        for (int p = 0; p < 8; p++) {
            const int orow = bm + tm * 8 + p;
            if (orow >= N_SPOTS) continue;
            float y[8];
#pragma unroll
            for (int q = 0; q < 8; q++) {
                const float h = facc[p][q] + bia[q];
                float v = (h - mu[q]) * rs[q] * ga[q] + be[q];
                y[q] = (v > 0.0f) ? v : expm1f(v);
            }
            float* dst = de_out + (size_t)orow * D_IN + fcol0 + tn * 8;
            *(float4*)dst       = *(float4*)&y[0];
            *(float4*)(dst + 4) = *(float4*)&y[4];
        }
    }
}

// ------------------------------- launch ----------------------------------------
extern "C" void kernel_launch(void* const* d_in, const int* in_sizes, int n_in,
                              void* d_out, int out_size) {
    const float* x     = (const float*)d_in[0];   // [10000,128]
    const float* xn    = (const float*)d_in[1];   // [60000,128]
    const float* sp    = (const float*)d_in[2];   // [10000,2]
    const float* W     = (const float*)d_in[3];   // [128,3000]
    const float* bias  = (const float*)d_in[4];   // [3000]
    const float* gamma = (const float*)d_in[5];   // [3000]
    const float* beta  = (const float*)d_in[6];   // [3000]

    float* out = (float*)d_out;
    float* z_out  = out;                                   // [10000,128]
    float* de_out = out + (size_t)N_SPOTS * D_LAT;         // [10000,3000]
    float* hr_out = de_out + (size_t)N_SPOTS * D_IN;       // [10000,768]

    int* idx_ptr;   cudaGetSymbolAddress((void**)&idx_ptr, g_idx);

    cudaFuncSetAttribute(gemm_kernel, cudaFuncAttributeMaxDynamicSharedMemorySize, GEMM_SMEM);

    zero_scratch<<<(D_LAT * D_LAT + 255) / 256, 256>>>();
    knn_count  <<<(N_SPOTS + 255) / 256, 256>>>((const float2*)sp);
    knn_scan   <<<1, 32>>>();
    knn_scatter<<<(N_SPOTS + 255) / 256, 256>>>((const float2*)sp);
    split_w    <<<(64 * D_IN + 255) / 256, 256>>>(W);
    knn_search <<<(N_SPOTS + 63) / 64, 64>>>(idx_ptr);
    agg_kernel <<<N_SPOTS, 128>>>(x, xn, z_out, hr_out);
    gram_kernel<<<GRAM_BLOCKS, 256>>>(z_out);
    stats_kernel<<<D_IN / 8, 256>>>(W, bias);
    gemm_kernel<<<dim3((D_IN + 127) / 128, (N_SPOTS + 127) / 128), 256, GEMM_SMEM>>>(
        z_out, W, bias, gamma, beta, de_out);
}